// round 12
// baseline (speedup 1.0000x reference)
#include <cuda_runtime.h>
#include <cuda_bf16.h>
#include <cstdint>

#define BB 512
#define QL 128
#define AL 512
#define EE 300
#define FF 400
#define VMAX 50000
#define NEG_INF (-1e30f)

#define KPAD 960            // 900 rounded up to 15 chunks of 64
#define FPAD 512            // 400 rounded up to 4 tiles of 128
#define APITCH 72           // smem row pitch in bf16 elems (64 + 8 pad = 144B)

// ---------------- scratch (device globals; no allocations allowed) ----------
__device__ __align__(16) __nv_bfloat16 g_Whi[FPAD * KPAD];   // weights split hi
__device__ __align__(16) __nv_bfloat16 g_Wlo[FPAD * KPAD];   // weights split lo
__device__ float g_Q[(size_t)BB * FF * QL];          // 104.8 MB
__device__ float g_A[(size_t)BB * FF * AL];          // 419 MB
__device__ float g_P[(size_t)BB * FF * QL];          // 104.8 MB
__device__ float g_maxQ[BB * QL];
__device__ float g_maxA[BB * AL];

__device__ __forceinline__ void atomicMaxF(float* a, float v) {
    if (v >= 0.f) atomicMax((int*)a, __float_as_int(v));
    else          atomicMin((unsigned int*)a, __float_as_uint(v));
}

// mma.sync m16n8k16 bf16 -> f32 accumulate (baseline PTX, assembles on compute_103)
__device__ __forceinline__ void mma16816(float* c, const uint32_t* a, const uint32_t* b) {
    asm volatile(
        "mma.sync.aligned.m16n8k16.row.col.f32.bf16.bf16.f32 "
        "{%0,%1,%2,%3}, {%4,%5,%6,%7}, {%8,%9}, {%0,%1,%2,%3};"
        : "+f"(c[0]), "+f"(c[1]), "+f"(c[2]), "+f"(c[3])
        : "r"(a[0]), "r"(a[1]), "r"(a[2]), "r"(a[3]), "r"(b[0]), "r"(b[1]));
}

// smem layout (dynamic): idx[130] ints, then 4 panels of 128 x APITCH bf16
#define IDX_OFF   0
#define A_HI_OFF  1024
#define PANEL_BYTES (128 * APITCH * 2)      // 18432
#define A_LO_OFF  (A_HI_OFF + PANEL_BYTES)
#define B_HI_OFF  (A_LO_OFF + PANEL_BYTES)
#define B_LO_OFF  (B_HI_OFF + PANEL_BYTES)
#define SMEM_TOTAL (B_LO_OFF + PANEL_BYTES)  // ~74.8 KB

// ---------------- K0: split weights to bf16 hi/lo + init maxes --------------
__global__ void init_kernel(const float* __restrict__ conv_w) {
    int i = blockIdx.x * 256 + threadIdx.x;
    if (i < FPAD * KPAD) {
        int f = i / KPAD, r = i - f * KPAD;
        float w = (f < FF && r < 900) ? conv_w[f * 900 + r] : 0.f;
        __nv_bfloat16 hi = __float2bfloat16(w);
        __nv_bfloat16 lo = __float2bfloat16(w - __bfloat162float(hi));
        g_Whi[i] = hi;
        g_Wlo[i] = lo;
    }
    if (i < BB * QL) g_maxQ[i] = NEG_INF;
    if (i < BB * AL) g_maxA[i] = NEG_INF;
}

// ---------------- K1: conv1d via bf16-split HMMA (mma.sync) -----------------
// grid: (ftile=4, seg=5, b=512); block 256 (8 warps).
// CTA tile: 128f x 128l; warp tile 64f x 32l (4 m16-tiles x 4 n8-tiles).
// K=960 in 15 chunks of 64 (4 k16 steps each); 3 split MMAs per k16.
__global__ __launch_bounds__(256) void conv_hmma_kernel(
    const int* __restrict__ qidx, const int* __restrict__ aidx,
    const float* __restrict__ emb, const float* __restrict__ bias)
{
    extern __shared__ char smem[];
    int* idx_s = (int*)(smem + IDX_OFF);
    __nv_bfloat16* Ah = (__nv_bfloat16*)(smem + A_HI_OFF);
    __nv_bfloat16* Al = (__nv_bfloat16*)(smem + A_LO_OFF);
    __nv_bfloat16* Bh = (__nv_bfloat16*)(smem + B_HI_OFF);
    __nv_bfloat16* Bl = (__nv_bfloat16*)(smem + B_LO_OFF);

    const int tid = threadIdx.x;
    const int wid = tid >> 5, lane = tid & 31;
    const int g = lane >> 2, tg = lane & 3;
    const int wm = wid >> 2, wn = wid & 3;          // warp grid 2m x 4n
    const int f0 = blockIdx.x * 128;
    const int seg = blockIdx.y;
    const int b = blockIdx.z;
    const bool isQ = (seg == 0);
    const int L = isQ ? QL : AL;
    const int l0 = isQ ? 0 : (seg - 1) * 128;
    const int* ip = isQ ? (qidx + b * QL) : (aidx + b * AL);
    float* outp = isQ ? (g_Q + (size_t)b * FF * QL) : (g_A + (size_t)b * FF * AL);

    for (int r = tid; r < 130; r += 256) {
        int gl = l0 - 1 + r;
        int id = -1;
        if (gl >= 0 && gl < L) {
            id = ip[gl];
            if (id < 0) id = 0;
            if (id > VMAX) id = VMAX;
        }
        idx_s[r] = id;
    }

    float acc[4][4][4];
    #pragma unroll
    for (int mt = 0; mt < 4; mt++)
        #pragma unroll
        for (int nt = 0; nt < 4; nt++)
            #pragma unroll
            for (int u = 0; u < 4; u++) acc[mt][nt][u] = 0.f;

    for (int c = 0; c < 15; c++) {
        const int r0 = c * 64;
        __syncthreads();   // previous step's mma reads done (and idx_s ready at c=0)

        // ---- A panels: 128f x 64k hi/lo from pre-split weights (vectorized)
        {
            const __nv_bfloat16* Wh = g_Whi + (size_t)f0 * KPAD + r0;
            const __nv_bfloat16* Wl = g_Wlo + (size_t)f0 * KPAD + r0;
            #pragma unroll
            for (int j = 0; j < 8; j++) {
                int idx = tid + j * 256;            // 0..2047 (u64 words, 16/row)
                int fl = idx >> 4, wc = idx & 15;
                uint64_t vh = *(const uint64_t*)(Wh + (size_t)fl * KPAD + wc * 4);
                uint64_t vl = *(const uint64_t*)(Wl + (size_t)fl * KPAD + wc * 4);
                *(uint64_t*)(Ah + fl * APITCH + wc * 4) = vh;
                *(uint64_t*)(Al + fl * APITCH + wc * 4) = vl;
            }
        }
        // ---- B panels: im2col gather 128l x 64r, split hi/lo
        #pragma unroll 4
        for (int j = 0; j < 32; j++) {
            int idx = tid + j * 256;                // 0..8191
            int l = idx >> 6, rr = idx & 63;
            int r = r0 + rr;
            float v = 0.f;
            if (r < 900) {
                int e = (int)((unsigned)r / 3u);
                int k = r - e * 3;
                int id = idx_s[l + k];
                if (id >= 0) v = __ldg(emb + (size_t)id * EE + e);
            }
            __nv_bfloat16 hi = __float2bfloat16(v);
            __nv_bfloat16 lo = __float2bfloat16(v - __bfloat162float(hi));
            Bh[l * APITCH + rr] = hi;
            Bl[l * APITCH + rr] = lo;
        }
        __syncthreads();

        // ---- 4 k16 steps of split-MMA
        #pragma unroll
        for (int ks = 0; ks < 4; ks++) {
            const int kb = ks * 16;
            uint32_t ah[4][4], al[4][4], bhf[4][2], blf[4][2];
            #pragma unroll
            for (int mt = 0; mt < 4; mt++) {
                int row = wm * 64 + mt * 16 + g;
                const __nv_bfloat16* p0 = Ah + row * APITCH + kb + tg * 2;
                const __nv_bfloat16* p1 = Ah + (row + 8) * APITCH + kb + tg * 2;
                ah[mt][0] = *(const uint32_t*)p0;
                ah[mt][1] = *(const uint32_t*)p1;
                ah[mt][2] = *(const uint32_t*)(p0 + 8);
                ah[mt][3] = *(const uint32_t*)(p1 + 8);
                const __nv_bfloat16* q0 = Al + row * APITCH + kb + tg * 2;
                const __nv_bfloat16* q1 = Al + (row + 8) * APITCH + kb + tg * 2;
                al[mt][0] = *(const uint32_t*)q0;
                al[mt][1] = *(const uint32_t*)q1;
                al[mt][2] = *(const uint32_t*)(q0 + 8);
                al[mt][3] = *(const uint32_t*)(q1 + 8);
            }
            #pragma unroll
            for (int nt = 0; nt < 4; nt++) {
                int col = wn * 32 + nt * 8 + g;
                const __nv_bfloat16* p = Bh + col * APITCH + kb + tg * 2;
                bhf[nt][0] = *(const uint32_t*)p;
                bhf[nt][1] = *(const uint32_t*)(p + 8);
                const __nv_bfloat16* q = Bl + col * APITCH + kb + tg * 2;
                blf[nt][0] = *(const uint32_t*)q;
                blf[nt][1] = *(const uint32_t*)(q + 8);
            }
            #pragma unroll
            for (int mt = 0; mt < 4; mt++)
                #pragma unroll
                for (int nt = 0; nt < 4; nt++) {
                    mma16816(acc[mt][nt], ah[mt], bhf[nt]);   // hi*hi
                    mma16816(acc[mt][nt], ah[mt], blf[nt]);   // hi*lo
                    mma16816(acc[mt][nt], al[mt], bhf[nt]);   // lo*hi
                }
        }
    }

    // ---- epilogue: D frag (c0,c1)=(row g), (c2,c3)=(row g+8); add bias -----
    #pragma unroll
    for (int mt = 0; mt < 4; mt++) {
        const int fr0 = f0 + wm * 64 + mt * 16 + g;
        const int fr1 = fr0 + 8;
        const float bv0 = (fr0 < FF) ? bias[fr0] : 0.f;
        const float bv1 = (fr1 < FF) ? bias[fr1] : 0.f;
        #pragma unroll
        for (int nt = 0; nt < 4; nt++) {
            const int l = l0 + wn * 32 + nt * 8 + tg * 2;
            if (fr0 < FF) {
                float2 v; v.x = acc[mt][nt][0] + bv0; v.y = acc[mt][nt][1] + bv0;
                *(float2*)(outp + (size_t)fr0 * L + l) = v;
            }
            if (fr1 < FF) {
                float2 v; v.x = acc[mt][nt][2] + bv1; v.y = acc[mt][nt][3] + bv1;
                *(float2*)(outp + (size_t)fr1 * L + l) = v;
            }
        }
    }
}

// ---------------- K2: P[b] = U^T @ Q[b]   ([400g x 128q], K=400f) -----------
__global__ __launch_bounds__(256) void pgemm_kernel(const float* __restrict__ Umat) {
    const int tid = threadIdx.x;
    const int tq = tid & 15, tg = tid >> 4;
    const int g0 = blockIdx.x * 80;
    const int b = blockIdx.y;
    __shared__ float Us[8 * 80];
    __shared__ float Qs[8 * 128];
    float acc[5][8];
    #pragma unroll
    for (int i = 0; i < 5; i++)
        #pragma unroll
        for (int j = 0; j < 8; j++) acc[i][j] = 0.f;

    const float* Qb = g_Q + (size_t)b * FF * QL;
    for (int fc = 0; fc < 50; fc++) {
        const int fbase = fc * 8;
        __syncthreads();
        for (int t = tid; t < 640; t += 256) {
            int gg = t % 80, ff2 = t / 80;
            Us[t] = Umat[(fbase + ff2) * 400 + g0 + gg];
        }
        for (int t = tid; t < 1024; t += 256) {
            int qq = t & 127, ff2 = t >> 7;
            Qs[t] = Qb[(size_t)(fbase + ff2) * QL + qq];
        }
        __syncthreads();
        #pragma unroll
        for (int ff2 = 0; ff2 < 8; ff2++) {
            float ur[5], qr[8];
            #pragma unroll
            for (int i = 0; i < 5; i++) ur[i] = Us[ff2 * 80 + tg + 16 * i];
            #pragma unroll
            for (int j = 0; j < 8; j++) qr[j] = Qs[ff2 * 128 + tq + 16 * j];
            #pragma unroll
            for (int i = 0; i < 5; i++)
                #pragma unroll
                for (int j = 0; j < 8; j++)
                    acc[i][j] += ur[i] * qr[j];
        }
    }
    float* Pb = g_P + (size_t)b * FF * QL;
    #pragma unroll
    for (int i = 0; i < 5; i++)
        #pragma unroll
        for (int j = 0; j < 8; j++)
            Pb[(size_t)(g0 + tg + 16 * i) * QL + tq + 16 * j] = acc[i][j];
}

// ---------------- K3: G = tanh(P^T A) tile + row/col maxes ------------------
__global__ __launch_bounds__(256) void gmax_kernel() {
    const int tid = threadIdx.x;
    const int ta = tid & 15, tq = tid >> 4;
    const int a0 = blockIdx.x * 128;
    const int b = blockIdx.y;
    __shared__ float Ps[8 * 128], As[8 * 128];
    __shared__ float smq[128], sma[128];

    float acc[8][8];
    #pragma unroll
    for (int i = 0; i < 8; i++)
        #pragma unroll
        for (int j = 0; j < 8; j++) acc[i][j] = 0.f;

    const float* Pb = g_P + (size_t)b * FF * QL;
    const float* Ab = g_A + (size_t)b * FF * AL;
    for (int gc = 0; gc < 50; gc++) {
        const int gbase = gc * 8;
        __syncthreads();
        for (int t = tid; t < 1024; t += 256) {
            int col = t & 127, gg = t >> 7;
            Ps[t] = Pb[(size_t)(gbase + gg) * QL + col];
            As[t] = Ab[(size_t)(gbase + gg) * AL + a0 + col];
        }
        __syncthreads();
        #pragma unroll
        for (int gg = 0; gg < 8; gg++) {
            float pr[8], ar[8];
            #pragma unroll
            for (int i = 0; i < 8; i++) pr[i] = Ps[gg * 128 + tq + 16 * i];
            #pragma unroll
            for (int j = 0; j < 8; j++) ar[j] = As[gg * 128 + ta + 16 * j];
            #pragma unroll
            for (int i = 0; i < 8; i++)
                #pragma unroll
                for (int j = 0; j < 8; j++)
                    acc[i][j] += pr[i] * ar[j];
        }
    }

    if (tid < 128) { smq[tid] = NEG_INF; sma[tid] = NEG_INF; }
    __syncthreads();

    float mq[8], ma[8];
    #pragma unroll
    for (int i = 0; i < 8; i++) mq[i] = NEG_INF;
    #pragma unroll
    for (int j = 0; j < 8; j++) ma[j] = NEG_INF;
    #pragma unroll
    for (int i = 0; i < 8; i++)
        #pragma unroll
        for (int j = 0; j < 8; j++) {
            float gv = tanhf(acc[i][j]);
            mq[i] = fmaxf(mq[i], gv);
            ma[j] = fmaxf(ma[j], gv);
        }
    #pragma unroll
    for (int i = 0; i < 8; i++) atomicMaxF(&smq[tq + 16 * i], mq[i]);
    #pragma unroll
    for (int j = 0; j < 8; j++) atomicMaxF(&sma[ta + 16 * j], ma[j]);
    __syncthreads();
    if (tid < 128) {
        atomicMaxF(&g_maxQ[b * QL + tid], smq[tid]);
        atomicMaxF(&g_maxA[b * AL + a0 + tid], sma[tid]);
    }
}

// ---------------- K4: softmax + pooled rQ/rA + cosine -----------------------
__global__ __launch_bounds__(256) void final_kernel(float* __restrict__ out) {
    const int tid = threadIdx.x;
    const int b = blockIdx.x;
    __shared__ float wq[128], wa[512], rq[400], ra[400], red[256];
    __shared__ float s_res[3];

    float v = (tid < 128) ? g_maxQ[b * QL + tid] : NEG_INF;
    red[tid] = v; __syncthreads();
    for (int s = 128; s > 0; s >>= 1) { if (tid < s) red[tid] = fmaxf(red[tid], red[tid + s]); __syncthreads(); }
    float m = red[0]; __syncthreads();
    float e = (tid < 128) ? __expf(v - m) : 0.f;
    red[tid] = e; __syncthreads();
    for (int s = 128; s > 0; s >>= 1) { if (tid < s) red[tid] += red[tid + s]; __syncthreads(); }
    float ssum = red[0]; __syncthreads();
    if (tid < 128) wq[tid] = e / ssum;

    float va0 = g_maxA[b * AL + tid], va1 = g_maxA[b * AL + 256 + tid];
    red[tid] = fmaxf(va0, va1); __syncthreads();
    for (int s = 128; s > 0; s >>= 1) { if (tid < s) red[tid] = fmaxf(red[tid], red[tid + s]); __syncthreads(); }
    float mA = red[0]; __syncthreads();
    float ea0 = __expf(va0 - mA), ea1 = __expf(va1 - mA);
    red[tid] = ea0 + ea1; __syncthreads();
    for (int s = 128; s > 0; s >>= 1) { if (tid < s) red[tid] += red[tid + s]; __syncthreads(); }
    float sA = red[0]; __syncthreads();
    wa[tid] = ea0 / sA; wa[256 + tid] = ea1 / sA;
    __syncthreads();

    const int lane = tid & 31, wd = tid >> 5, sub = lane & 7, fl = lane >> 3;
    const float* Qb = g_Q + (size_t)b * FF * QL;
    const float* Ab = g_A + (size_t)b * FF * AL;
    for (int fb = wd * 4; fb < 400; fb += 32) {
        const int f = fb + fl;
        float accq = 0.f;
        for (int q = sub; q < QL; q += 8) accq += Qb[(size_t)f * QL + q] * wq[q];
        accq += __shfl_xor_sync(0xffffffffu, accq, 1);
        accq += __shfl_xor_sync(0xffffffffu, accq, 2);
        accq += __shfl_xor_sync(0xffffffffu, accq, 4);
        if (sub == 0) rq[f] = accq;
        float acca = 0.f;
        for (int a = sub; a < AL; a += 8) acca += Ab[(size_t)f * AL + a] * wa[a];
        acca += __shfl_xor_sync(0xffffffffu, acca, 1);
        acca += __shfl_xor_sync(0xffffffffu, acca, 2);
        acca += __shfl_xor_sync(0xffffffffu, acca, 4);
        if (sub == 0) ra[f] = acca;
    }
    __syncthreads();

    float dqa = 0.f, dqq = 0.f, daa = 0.f;
    for (int f = tid; f < 400; f += 256) {
        float x = rq[f], y = ra[f];
        dqa += x * y; dqq += x * x; daa += y * y;
    }
    red[tid] = dqa; __syncthreads();
    for (int s = 128; s > 0; s >>= 1) { if (tid < s) red[tid] += red[tid + s]; __syncthreads(); }
    if (tid == 0) s_res[0] = red[0];
    __syncthreads();
    red[tid] = dqq; __syncthreads();
    for (int s = 128; s > 0; s >>= 1) { if (tid < s) red[tid] += red[tid + s]; __syncthreads(); }
    if (tid == 0) s_res[1] = red[0];
    __syncthreads();
    red[tid] = daa; __syncthreads();
    for (int s = 128; s > 0; s >>= 1) { if (tid < s) red[tid] += red[tid + s]; __syncthreads(); }
    if (tid == 0) {
        s_res[2] = red[0];
        float nQ = fmaxf(sqrtf(s_res[1]), 1e-8f);
        float nA = fmaxf(sqrtf(s_res[2]), 1e-8f);
        out[b] = s_res[0] / (nQ * nA);
    }
}

// ---------------- launch -----------------------------------------------------
extern "C" void kernel_launch(void* const* d_in, const int* in_sizes, int n_in,
                              void* d_out, int out_size) {
    (void)in_sizes; (void)n_in; (void)out_size;
    const int*   question = (const int*)d_in[0];
    const int*   answer   = (const int*)d_in[1];
    const float* emb      = (const float*)d_in[2];
    const float* conv_w   = (const float*)d_in[3];
    const float* conv_b   = (const float*)d_in[4];
    const float* Umat     = (const float*)d_in[5];
    float* out = (float*)d_out;

    cudaFuncSetAttribute(conv_hmma_kernel,
                         cudaFuncAttributeMaxDynamicSharedMemorySize, SMEM_TOTAL);

    init_kernel<<<(FPAD * KPAD + 255) / 256, 256>>>(conv_w);
    conv_hmma_kernel<<<dim3(4, 5, 512), 256, SMEM_TOTAL>>>(question, answer, emb, conv_b);
    pgemm_kernel<<<dim3(5, 512), 256>>>(Umat);
    gmax_kernel<<<dim3(4, 512), 256>>>();
    final_kernel<<<512, 256>>>(out);
}

// round 13
// speedup vs baseline: 1.5239x; 1.5239x over previous
#include <cuda_runtime.h>
#include <cstdint>

#define BB 512
#define QL 128
#define AL 512
#define EE 300
#define FF 400
#define VV 50001
#define VMAX 50000
#define NEG_INF (-1e30f)

// ---------------- scratch (device globals; no allocations allowed) ----------
__device__ float g_Wt2[EE * 1200];                   // Wt2[e][k*400+f] (1.44 MB)
__device__ float g_T[(size_t)VV * 1200];             // T[v][k][f] (240 MB)
__device__ float g_Q[(size_t)BB * FF * QL];          // 104.8 MB
__device__ float g_A[(size_t)BB * FF * AL];          // 419 MB
__device__ float g_P[(size_t)BB * FF * QL];          // 104.8 MB
__device__ float g_maxQ[BB * QL];
__device__ float g_maxA[BB * AL];

__device__ __forceinline__ void atomicMaxF(float* a, float v) {
    if (v >= 0.f) atomicMax((int*)a, __float_as_int(v));
    else          atomicMin((unsigned int*)a, __float_as_uint(v));
}

// ---------------- K0: build Wt2 + init maxes --------------------------------
// Wt2[e][k*400+f] = conv_w[f*900 + e*3 + k]
__global__ void init_kernel(const float* __restrict__ conv_w) {
    int i = blockIdx.x * 256 + threadIdx.x;
    if (i < EE * 1200) {
        int e = i / 1200, rem = i - e * 1200;
        int k = rem / 400, f = rem - k * 400;
        g_Wt2[i] = conv_w[f * 900 + e * 3 + k];
    }
    if (i < BB * QL) g_maxQ[i] = NEG_INF;
    if (i < BB * AL) g_maxA[i] = NEG_INF;
}

// ---------------- K1a: T = emb @ Wt2  ([50001 x 300] @ [300 x 1200]) --------
// grid: (ntile=15, vtile=391); block 256; per-thread 8v x 5n.
__global__ __launch_bounds__(256) void tgemm_kernel(const float* __restrict__ emb) {
    const int tid = threadIdx.x;
    const int tn = tid & 15, tv = tid >> 4;
    const int n0 = blockIdx.x * 80;
    const int v0 = blockIdx.y * 128;
    __shared__ float Es[10 * 128];     // [e_local][v_local]
    __shared__ float Ws[10 * 80];      // [e_local][n_local]

    float acc[8][5];
    #pragma unroll
    for (int i = 0; i < 8; i++)
        #pragma unroll
        for (int j = 0; j < 5; j++) acc[i][j] = 0.f;

    const int vld = tid >> 1, part = tid & 1;   // each thread loads 5 e for one v
    for (int ec = 0; ec < 30; ec++) {
        const int e0 = ec * 10;
        __syncthreads();
        {
            int vv = v0 + vld; if (vv > VMAX) vv = VMAX;
            const float* er = emb + (size_t)vv * EE + e0 + part * 5;
            #pragma unroll
            for (int u = 0; u < 5; u++)
                Es[(part * 5 + u) * 128 + vld] = er[u];
        }
        for (int t = tid; t < 800; t += 256) {
            int e = t / 80, n = t - e * 80;
            Ws[t] = g_Wt2[(e0 + e) * 1200 + n0 + n];
        }
        __syncthreads();
        #pragma unroll
        for (int e = 0; e < 10; e++) {
            float vr[8], wr[5];
            #pragma unroll
            for (int i = 0; i < 8; i++) vr[i] = Es[e * 128 + tv + 16 * i];
            #pragma unroll
            for (int j = 0; j < 5; j++) wr[j] = Ws[e * 80 + tn + 16 * j];
            #pragma unroll
            for (int i = 0; i < 8; i++)
                #pragma unroll
                for (int j = 0; j < 5; j++)
                    acc[i][j] += vr[i] * wr[j];
        }
    }
    #pragma unroll
    for (int i = 0; i < 8; i++) {
        const int v = v0 + tv + 16 * i;
        if (v <= VMAX) {
            float* op = g_T + (size_t)v * 1200 + n0 + tn;
            #pragma unroll
            for (int j = 0; j < 5; j++) op[16 * j] = acc[i][j];
        }
    }
}

// ---------------- K1b: gather-conv: out[f,l] = bias[f] + sum_k T[tok][k][f] -
// grid: (ltile=20, b=512); block 256. ltile 0..3 -> Q, 4..19 -> A.
// smem acc plane [32 l][401 pitch] fp32; one syncthreads per token row.
#define GPITCH 401
#define GA_SMEM (32 * GPITCH * 4)
__global__ __launch_bounds__(256) void gatherconv_kernel(
    const int* __restrict__ qidx, const int* __restrict__ aidx,
    const float* __restrict__ bias)
{
    extern __shared__ float acc[];
    __shared__ int toks[34];
    const int tid = threadIdx.x;
    const int bx = blockIdx.x, b = blockIdx.y;
    const bool isQ = (bx < 4);
    const int L = isQ ? QL : AL;
    const int l0 = (isQ ? bx : bx - 4) * 32;
    const int* ip = isQ ? (qidx + b * QL) : (aidx + b * AL);
    float* outp = isQ ? (g_Q + (size_t)b * FF * QL) : (g_A + (size_t)b * FF * AL);

    if (tid < 34) {
        int p = l0 - 1 + tid;
        int id = 0;                         // token 0 row of T is all zeros
        if (p >= 0 && p < L) {
            id = ip[p];
            if (id < 0) id = 0;
            if (id > VMAX) id = VMAX;
        }
        toks[tid] = id;
    }
    // init acc = bias
    for (int idx = tid; idx < 12800; idx += 256) {
        int f = idx >> 5, l = idx & 31;
        acc[l * GPITCH + f] = bias[f];
    }
    // per-thread element slots (fixed (k,f) ownership)
    int kk[5], ff[5];
    #pragma unroll
    for (int j = 0; j < 5; j++) {
        int i = tid + 256 * j;
        int k = (i < 400) ? 0 : (i < 800 ? 1 : 2);
        kk[j] = k; ff[j] = i - k * 400;
    }
    __syncthreads();

    for (int pi = 0; pi < 34; pi++) {
        const float* row = g_T + (size_t)toks[pi] * 1200;
        float vals[5];
        #pragma unroll
        for (int j = 0; j < 5; j++) {
            int i = tid + 256 * j;
            vals[j] = (i < 1200) ? __ldg(row + i) : 0.f;
        }
        #pragma unroll
        for (int j = 0; j < 5; j++) {
            int i = tid + 256 * j;
            int dl = pi - kk[j];
            if (i < 1200 && dl >= 0 && dl < 32)
                acc[dl * GPITCH + ff[j]] += vals[j];
        }
        __syncthreads();                   // cross-k same-cell writers serialize
    }

    for (int idx = tid; idx < 12800; idx += 256) {
        int f = idx >> 5, l = idx & 31;    // warp = one f row of 32 l (coalesced)
        outp[(size_t)f * L + l0 + l] = acc[l * GPITCH + f];
    }
}

// ---------------- K2: P[b] = U^T @ Q[b]   ([400g x 128q], K=400f) -----------
__global__ __launch_bounds__(256) void pgemm_kernel(const float* __restrict__ Umat) {
    const int tid = threadIdx.x;
    const int tq = tid & 15, tg = tid >> 4;
    const int g0 = blockIdx.x * 80;
    const int b = blockIdx.y;
    __shared__ float Us[8 * 80];
    __shared__ float Qs[8 * 128];
    float acc[5][8];
    #pragma unroll
    for (int i = 0; i < 5; i++)
        #pragma unroll
        for (int j = 0; j < 8; j++) acc[i][j] = 0.f;

    const float* Qb = g_Q + (size_t)b * FF * QL;
    for (int fc = 0; fc < 50; fc++) {
        const int fbase = fc * 8;
        __syncthreads();
        for (int t = tid; t < 640; t += 256) {
            int gg = t % 80, ff2 = t / 80;
            Us[t] = Umat[(fbase + ff2) * 400 + g0 + gg];
        }
        for (int t = tid; t < 1024; t += 256) {
            int qq = t & 127, ff2 = t >> 7;
            Qs[t] = Qb[(size_t)(fbase + ff2) * QL + qq];
        }
        __syncthreads();
        #pragma unroll
        for (int ff2 = 0; ff2 < 8; ff2++) {
            float ur[5], qr[8];
            #pragma unroll
            for (int i = 0; i < 5; i++) ur[i] = Us[ff2 * 80 + tg + 16 * i];
            #pragma unroll
            for (int j = 0; j < 8; j++) qr[j] = Qs[ff2 * 128 + tq + 16 * j];
            #pragma unroll
            for (int i = 0; i < 5; i++)
                #pragma unroll
                for (int j = 0; j < 8; j++)
                    acc[i][j] += ur[i] * qr[j];
        }
    }
    float* Pb = g_P + (size_t)b * FF * QL;
    #pragma unroll
    for (int i = 0; i < 5; i++)
        #pragma unroll
        for (int j = 0; j < 8; j++)
            Pb[(size_t)(g0 + tg + 16 * i) * QL + tq + 16 * j] = acc[i][j];
}

// ---------------- K3: G = tanh(P^T A) tile + row/col maxes ------------------
__global__ __launch_bounds__(256) void gmax_kernel() {
    const int tid = threadIdx.x;
    const int ta = tid & 15, tq = tid >> 4;
    const int a0 = blockIdx.x * 128;
    const int b = blockIdx.y;
    __shared__ float Ps[8 * 128], As[8 * 128];
    __shared__ float smq[128], sma[128];

    float acc[8][8];
    #pragma unroll
    for (int i = 0; i < 8; i++)
        #pragma unroll
        for (int j = 0; j < 8; j++) acc[i][j] = 0.f;

    const float* Pb = g_P + (size_t)b * FF * QL;
    const float* Ab = g_A + (size_t)b * FF * AL;
    for (int gc = 0; gc < 50; gc++) {
        const int gbase = gc * 8;
        __syncthreads();
        for (int t = tid; t < 1024; t += 256) {
            int col = t & 127, gg = t >> 7;
            Ps[t] = Pb[(size_t)(gbase + gg) * QL + col];
            As[t] = Ab[(size_t)(gbase + gg) * AL + a0 + col];
        }
        __syncthreads();
        #pragma unroll
        for (int gg = 0; gg < 8; gg++) {
            float pr[8], ar[8];
            #pragma unroll
            for (int i = 0; i < 8; i++) pr[i] = Ps[gg * 128 + tq + 16 * i];
            #pragma unroll
            for (int j = 0; j < 8; j++) ar[j] = As[gg * 128 + ta + 16 * j];
            #pragma unroll
            for (int i = 0; i < 8; i++)
                #pragma unroll
                for (int j = 0; j < 8; j++)
                    acc[i][j] += pr[i] * ar[j];
        }
    }

    if (tid < 128) { smq[tid] = NEG_INF; sma[tid] = NEG_INF; }
    __syncthreads();

    float mq[8], ma[8];
    #pragma unroll
    for (int i = 0; i < 8; i++) mq[i] = NEG_INF;
    #pragma unroll
    for (int j = 0; j < 8; j++) ma[j] = NEG_INF;
    #pragma unroll
    for (int i = 0; i < 8; i++)
        #pragma unroll
        for (int j = 0; j < 8; j++) {
            float gv = tanhf(acc[i][j]);
            mq[i] = fmaxf(mq[i], gv);
            ma[j] = fmaxf(ma[j], gv);
        }
    #pragma unroll
    for (int i = 0; i < 8; i++) atomicMaxF(&smq[tq + 16 * i], mq[i]);
    #pragma unroll
    for (int j = 0; j < 8; j++) atomicMaxF(&sma[ta + 16 * j], ma[j]);
    __syncthreads();
    if (tid < 128) {
        atomicMaxF(&g_maxQ[b * QL + tid], smq[tid]);
        atomicMaxF(&g_maxA[b * AL + a0 + tid], sma[tid]);
    }
}

// ---------------- K4: softmax + pooled rQ/rA + cosine -----------------------
__global__ __launch_bounds__(256) void final_kernel(float* __restrict__ out) {
    const int tid = threadIdx.x;
    const int b = blockIdx.x;
    __shared__ float wq[128], wa[512], rq[400], ra[400], red[256];
    __shared__ float s_res[3];

    float v = (tid < 128) ? g_maxQ[b * QL + tid] : NEG_INF;
    red[tid] = v; __syncthreads();
    for (int s = 128; s > 0; s >>= 1) { if (tid < s) red[tid] = fmaxf(red[tid], red[tid + s]); __syncthreads(); }
    float m = red[0]; __syncthreads();
    float e = (tid < 128) ? __expf(v - m) : 0.f;
    red[tid] = e; __syncthreads();
    for (int s = 128; s > 0; s >>= 1) { if (tid < s) red[tid] += red[tid + s]; __syncthreads(); }
    float ssum = red[0]; __syncthreads();
    if (tid < 128) wq[tid] = e / ssum;

    float va0 = g_maxA[b * AL + tid], va1 = g_maxA[b * AL + 256 + tid];
    red[tid] = fmaxf(va0, va1); __syncthreads();
    for (int s = 128; s > 0; s >>= 1) { if (tid < s) red[tid] = fmaxf(red[tid], red[tid + s]); __syncthreads(); }
    float mA = red[0]; __syncthreads();
    float ea0 = __expf(va0 - mA), ea1 = __expf(va1 - mA);
    red[tid] = ea0 + ea1; __syncthreads();
    for (int s = 128; s > 0; s >>= 1) { if (tid < s) red[tid] += red[tid + s]; __syncthreads(); }
    float sA = red[0]; __syncthreads();
    wa[tid] = ea0 / sA; wa[256 + tid] = ea1 / sA;
    __syncthreads();

    const int lane = tid & 31, wd = tid >> 5, sub = lane & 7, fl = lane >> 3;
    const float* Qb = g_Q + (size_t)b * FF * QL;
    const float* Ab = g_A + (size_t)b * FF * AL;
    for (int fb = wd * 4; fb < 400; fb += 32) {
        const int f = fb + fl;
        float accq = 0.f;
        for (int q = sub; q < QL; q += 8) accq += Qb[(size_t)f * QL + q] * wq[q];
        accq += __shfl_xor_sync(0xffffffffu, accq, 1);
        accq += __shfl_xor_sync(0xffffffffu, accq, 2);
        accq += __shfl_xor_sync(0xffffffffu, accq, 4);
        if (sub == 0) rq[f] = accq;
        float acca = 0.f;
        for (int a = sub; a < AL; a += 8) acca += Ab[(size_t)f * AL + a] * wa[a];
        acca += __shfl_xor_sync(0xffffffffu, acca, 1);
        acca += __shfl_xor_sync(0xffffffffu, acca, 2);
        acca += __shfl_xor_sync(0xffffffffu, acca, 4);
        if (sub == 0) ra[f] = acca;
    }
    __syncthreads();

    float dqa = 0.f, dqq = 0.f, daa = 0.f;
    for (int f = tid; f < 400; f += 256) {
        float x = rq[f], y = ra[f];
        dqa += x * y; dqq += x * x; daa += y * y;
    }
    red[tid] = dqa; __syncthreads();
    for (int s = 128; s > 0; s >>= 1) { if (tid < s) red[tid] += red[tid + s]; __syncthreads(); }
    if (tid == 0) s_res[0] = red[0];
    __syncthreads();
    red[tid] = dqq; __syncthreads();
    for (int s = 128; s > 0; s >>= 1) { if (tid < s) red[tid] += red[tid + s]; __syncthreads(); }
    if (tid == 0) s_res[1] = red[0];
    __syncthreads();
    red[tid] = daa; __syncthreads();
    for (int s = 128; s > 0; s >>= 1) { if (tid < s) red[tid] += red[tid + s]; __syncthreads(); }
    if (tid == 0) {
        s_res[2] = red[0];
        float nQ = fmaxf(sqrtf(s_res[1]), 1e-8f);
        float nA = fmaxf(sqrtf(s_res[2]), 1e-8f);
        out[b] = s_res[0] / (nQ * nA);
    }
}

// ---------------- launch -----------------------------------------------------
extern "C" void kernel_launch(void* const* d_in, const int* in_sizes, int n_in,
                              void* d_out, int out_size) {
    (void)in_sizes; (void)n_in; (void)out_size;
    const int*   question = (const int*)d_in[0];
    const int*   answer   = (const int*)d_in[1];
    const float* emb      = (const float*)d_in[2];
    const float* conv_w   = (const float*)d_in[3];
    const float* conv_b   = (const float*)d_in[4];
    const float* Umat     = (const float*)d_in[5];
    float* out = (float*)d_out;

    cudaFuncSetAttribute(gatherconv_kernel,
                         cudaFuncAttributeMaxDynamicSharedMemorySize, GA_SMEM);

    init_kernel<<<(EE * 1200 + 255) / 256, 256>>>(conv_w);
    tgemm_kernel<<<dim3(15, 391), 256>>>(emb);
    gatherconv_kernel<<<dim3(20, 512), 256, GA_SMEM>>>(question, answer, conv_b);
    pgemm_kernel<<<dim3(5, 512), 256>>>(Umat);
    gmax_kernel<<<dim3(4, 512), 256>>>();
    final_kernel<<<512, 256>>>(out);
}

// round 14
// speedup vs baseline: 2.8859x; 1.8937x over previous
#include <cuda_runtime.h>
#include <cstdint>

#define BB 512
#define QL 128
#define AL 512
#define EE 300
#define FF 400
#define VV 50001
#define VMAX 50000
#define VPADT 50048           // 391*128
#define NEG_INF (-1e30f)

// ---------------- scratch (device globals; no allocations allowed) ----------
__device__ float g_Wt2[EE * 1200];                   // Wt2[e][k*400+f] (1.44 MB)
__device__ float g_embT[(size_t)EE * VPADT];         // emb transposed (60 MB)
__device__ float g_T[(size_t)VV * 1200];             // T[v][k][f] (240 MB)
__device__ float g_Q[(size_t)BB * FF * QL];          // 104.8 MB
__device__ float g_A[(size_t)BB * FF * AL];          // 419 MB
__device__ float g_P[(size_t)BB * FF * QL];          // 104.8 MB
__device__ float g_maxQ[BB * QL];
__device__ float g_maxA[BB * AL];

__device__ __forceinline__ void atomicMaxF(float* a, float v) {
    if (v >= 0.f) atomicMax((int*)a, __float_as_int(v));
    else          atomicMin((unsigned int*)a, __float_as_uint(v));
}

// ---------------- K0: build Wt2 + init maxes --------------------------------
__global__ void init_kernel(const float* __restrict__ conv_w) {
    int i = blockIdx.x * 256 + threadIdx.x;
    if (i < EE * 1200) {
        int e = i / 1200, rem = i - e * 1200;
        int k = rem / 400, f = rem - k * 400;
        g_Wt2[i] = conv_w[f * 900 + e * 3 + k];
    }
    if (i < BB * QL) g_maxQ[i] = NEG_INF;
    if (i < BB * AL) g_maxA[i] = NEG_INF;
}

// ---------------- K0b: transpose emb -> embT[e][v] --------------------------
__global__ void transpose_emb_kernel(const float* __restrict__ emb) {
    __shared__ float tile[32][33];
    const int v0 = blockIdx.x * 32, e0 = blockIdx.y * 32;
    const int tx = threadIdx.x, ty = threadIdx.y;
    #pragma unroll
    for (int i = ty; i < 32; i += 8) {
        int v = v0 + i, e = e0 + tx;
        tile[i][tx] = (v < VV && e < EE) ? emb[(size_t)v * EE + e] : 0.f;
    }
    __syncthreads();
    #pragma unroll
    for (int i = ty; i < 32; i += 8) {
        int e = e0 + i, v = v0 + tx;
        if (e < EE) g_embT[(size_t)e * VPADT + v] = tile[tx][i];
    }
}

// ---------------- K1a: T = emb @ Wt2  ([50001 x 300] @ [300 x 1200]) --------
// grid: (ntile=15, vtile=391); block 256; per-thread 8v(contig) x 5n(contig).
__global__ __launch_bounds__(256) void tgemm_kernel() {
    const int tid = threadIdx.x;
    const int tn = tid & 15, tv = tid >> 4;
    const int n0 = blockIdx.x * 80;
    const int v0 = blockIdx.y * 128;
    __shared__ float Es[10 * 128];     // [e_local][v_local]
    __shared__ float Ws[10 * 80];      // [e_local][n_local]

    float acc[8][5];
    #pragma unroll
    for (int i = 0; i < 8; i++)
        #pragma unroll
        for (int j = 0; j < 5; j++) acc[i][j] = 0.f;

    for (int ec = 0; ec < 30; ec++) {
        const int e0 = ec * 10;
        __syncthreads();
        #pragma unroll
        for (int u = 0; u < 5; u++) {
            int idx = tid + 256 * u;            // 0..1279
            int e = idx >> 7, v = idx & 127;
            Es[idx] = g_embT[(size_t)(e0 + e) * VPADT + v0 + v];  // coalesced
        }
        #pragma unroll
        for (int t = tid; t < 800; t += 256) {
            int e = t / 80, n = t - e * 80;
            Ws[t] = g_Wt2[(e0 + e) * 1200 + n0 + n];
        }
        __syncthreads();
        #pragma unroll
        for (int e = 0; e < 10; e++) {
            float4 va = *(const float4*)&Es[e * 128 + tv * 8];
            float4 vb = *(const float4*)&Es[e * 128 + tv * 8 + 4];
            float vr[8] = {va.x, va.y, va.z, va.w, vb.x, vb.y, vb.z, vb.w};
            float wr[5];
            #pragma unroll
            for (int j = 0; j < 5; j++) wr[j] = Ws[e * 80 + tn * 5 + j];
            #pragma unroll
            for (int i = 0; i < 8; i++)
                #pragma unroll
                for (int j = 0; j < 5; j++)
                    acc[i][j] += vr[i] * wr[j];
        }
    }
    #pragma unroll
    for (int i = 0; i < 8; i++) {
        const int v = v0 + tv * 8 + i;
        if (v <= VMAX) {
            float* op = g_T + (size_t)v * 1200 + n0 + tn * 5;
            #pragma unroll
            for (int j = 0; j < 5; j++) op[j] = acc[i][j];
        }
    }
}

// ---------------- K1b: gather-conv: out[f,l] = bias[f] + sum_k T[tok][k][f] -
#define GPITCH 401
#define GA_SMEM (32 * GPITCH * 4)
__global__ __launch_bounds__(256) void gatherconv_kernel(
    const int* __restrict__ qidx, const int* __restrict__ aidx,
    const float* __restrict__ bias)
{
    extern __shared__ float acc[];
    __shared__ int toks[34];
    const int tid = threadIdx.x;
    const int bx = blockIdx.x, b = blockIdx.y;
    const bool isQ = (bx < 4);
    const int L = isQ ? QL : AL;
    const int l0 = (isQ ? bx : bx - 4) * 32;
    const int* ip = isQ ? (qidx + b * QL) : (aidx + b * AL);
    float* outp = isQ ? (g_Q + (size_t)b * FF * QL) : (g_A + (size_t)b * FF * AL);

    if (tid < 34) {
        int p = l0 - 1 + tid;
        int id = 0;                         // token 0 row of T is all zeros
        if (p >= 0 && p < L) {
            id = ip[p];
            if (id < 0) id = 0;
            if (id > VMAX) id = VMAX;
        }
        toks[tid] = id;
    }
    for (int idx = tid; idx < 12800; idx += 256) {
        int f = idx >> 5, l = idx & 31;
        acc[l * GPITCH + f] = bias[f];
    }
    int kk[5], ff[5];
    #pragma unroll
    for (int j = 0; j < 5; j++) {
        int i = tid + 256 * j;
        int k = (i < 400) ? 0 : (i < 800 ? 1 : 2);
        kk[j] = k; ff[j] = i - k * 400;
    }
    __syncthreads();

    for (int pi = 0; pi < 34; pi++) {
        const float* row = g_T + (size_t)toks[pi] * 1200;
        float vals[5];
        #pragma unroll
        for (int j = 0; j < 5; j++) {
            int i = tid + 256 * j;
            vals[j] = (i < 1200) ? __ldg(row + i) : 0.f;
        }
        #pragma unroll
        for (int j = 0; j < 5; j++) {
            int i = tid + 256 * j;
            int dl = pi - kk[j];
            if (i < 1200 && dl >= 0 && dl < 32)
                acc[dl * GPITCH + ff[j]] += vals[j];
        }
        __syncthreads();
    }

    for (int idx = tid; idx < 12800; idx += 256) {
        int f = idx >> 5, l = idx & 31;
        outp[(size_t)f * L + l0 + l] = acc[l * GPITCH + f];
    }
}

// ---------------- K2: P[b] = U^T @ Q[b]   ([400g x 128q], K=400f) -----------
// grid: (gtile=4 x 128g, b=512); block 256; per-thread 8g x 8q contiguous.
__global__ __launch_bounds__(256) void pgemm_kernel(const float* __restrict__ Umat) {
    const int tid = threadIdx.x;
    const int tq = tid & 15, tg = tid >> 4;
    const int g0 = blockIdx.x * 128;
    const int b = blockIdx.y;
    __shared__ float Us[8 * 128];
    __shared__ float Qs[8 * 128];
    float acc[8][8];
    #pragma unroll
    for (int i = 0; i < 8; i++)
        #pragma unroll
        for (int j = 0; j < 8; j++) acc[i][j] = 0.f;

    const float* Qb = g_Q + (size_t)b * FF * QL;
    const int fq = tid >> 5, q4 = (tid & 31) * 4;     // float4 loader mapping
    for (int fc = 0; fc < 50; fc++) {
        const int fbase = fc * 8;
        __syncthreads();
        #pragma unroll
        for (int u = 0; u < 4; u++) {
            int t = tid + 256 * u;                    // 0..1023
            int f = t >> 7, g = t & 127;
            Us[t] = (g0 + g < FF) ? Umat[(fbase + f) * FF + g0 + g] : 0.f;
        }
        *(float4*)&Qs[fq * 128 + q4] = *(const float4*)(Qb + (size_t)(fbase + fq) * QL + q4);
        __syncthreads();
        #pragma unroll
        for (int f = 0; f < 8; f++) {
            float4 ua = *(const float4*)&Us[f * 128 + tg * 8];
            float4 ub = *(const float4*)&Us[f * 128 + tg * 8 + 4];
            float4 qa = *(const float4*)&Qs[f * 128 + tq * 8];
            float4 qb = *(const float4*)&Qs[f * 128 + tq * 8 + 4];
            float ur[8] = {ua.x, ua.y, ua.z, ua.w, ub.x, ub.y, ub.z, ub.w};
            float qr[8] = {qa.x, qa.y, qa.z, qa.w, qb.x, qb.y, qb.z, qb.w};
            #pragma unroll
            for (int i = 0; i < 8; i++)
                #pragma unroll
                for (int j = 0; j < 8; j++)
                    acc[i][j] += ur[i] * qr[j];
        }
    }
    float* Pb = g_P + (size_t)b * FF * QL;
    #pragma unroll
    for (int i = 0; i < 8; i++) {
        const int g = g0 + tg * 8 + i;
        if (g < FF) {
            float4 v0 = {acc[i][0], acc[i][1], acc[i][2], acc[i][3]};
            float4 v1 = {acc[i][4], acc[i][5], acc[i][6], acc[i][7]};
            *(float4*)(Pb + (size_t)g * QL + tq * 8) = v0;
            *(float4*)(Pb + (size_t)g * QL + tq * 8 + 4) = v1;
        }
    }
}

// ---------------- K3: G = tanh(P^T A) tile + row/col maxes ------------------
// grid: (atile=4, b=512); block 256; per-thread 8q x 8a contiguous.
__global__ __launch_bounds__(256) void gmax_kernel() {
    const int tid = threadIdx.x;
    const int ta = tid & 15, tq = tid >> 4;
    const int a0 = blockIdx.x * 128;
    const int b = blockIdx.y;
    __shared__ float Ps[8 * 128], As[8 * 128];
    __shared__ float smq[128], sma[128];

    float acc[8][8];
    #pragma unroll
    for (int i = 0; i < 8; i++)
        #pragma unroll
        for (int j = 0; j < 8; j++) acc[i][j] = 0.f;

    const float* Pb = g_P + (size_t)b * FF * QL;
    const float* Ab = g_A + (size_t)b * FF * AL;
    const int fg = tid >> 5, c4 = (tid & 31) * 4;
    for (int gc = 0; gc < 50; gc++) {
        const int gbase = gc * 8;
        __syncthreads();
        *(float4*)&Ps[fg * 128 + c4] = *(const float4*)(Pb + (size_t)(gbase + fg) * QL + c4);
        *(float4*)&As[fg * 128 + c4] = *(const float4*)(Ab + (size_t)(gbase + fg) * AL + a0 + c4);
        __syncthreads();
        #pragma unroll
        for (int g = 0; g < 8; g++) {
            float4 pa = *(const float4*)&Ps[g * 128 + tq * 8];
            float4 pb = *(const float4*)&Ps[g * 128 + tq * 8 + 4];
            float4 aa = *(const float4*)&As[g * 128 + ta * 8];
            float4 ab = *(const float4*)&As[g * 128 + ta * 8 + 4];
            float pr[8] = {pa.x, pa.y, pa.z, pa.w, pb.x, pb.y, pb.z, pb.w};
            float ar[8] = {aa.x, aa.y, aa.z, aa.w, ab.x, ab.y, ab.z, ab.w};
            #pragma unroll
            for (int i = 0; i < 8; i++)
                #pragma unroll
                for (int j = 0; j < 8; j++)
                    acc[i][j] += pr[i] * ar[j];
        }
    }

    if (tid < 128) { smq[tid] = NEG_INF; sma[tid] = NEG_INF; }
    __syncthreads();

    // tanh is monotonic: max(tanh(x)) = tanh(max(x))
    float mq[8], ma[8];
    #pragma unroll
    for (int i = 0; i < 8; i++) mq[i] = NEG_INF;
    #pragma unroll
    for (int j = 0; j < 8; j++) ma[j] = NEG_INF;
    #pragma unroll
    for (int i = 0; i < 8; i++)
        #pragma unroll
        for (int j = 0; j < 8; j++) {
            mq[i] = fmaxf(mq[i], acc[i][j]);
            ma[j] = fmaxf(ma[j], acc[i][j]);
        }
    #pragma unroll
    for (int i = 0; i < 8; i++) atomicMaxF(&smq[tq * 8 + i], tanhf(mq[i]));
    #pragma unroll
    for (int j = 0; j < 8; j++) atomicMaxF(&sma[ta * 8 + j], tanhf(ma[j]));
    __syncthreads();
    if (tid < 128) {
        atomicMaxF(&g_maxQ[b * QL + tid], smq[tid]);
        atomicMaxF(&g_maxA[b * AL + a0 + tid], sma[tid]);
    }
}

// ---------------- K4: softmax + pooled rQ/rA + cosine -----------------------
__global__ __launch_bounds__(256) void final_kernel(float* __restrict__ out) {
    const int tid = threadIdx.x;
    const int b = blockIdx.x;
    __shared__ float wq[128], wa[512], rq[400], ra[400], red[256];
    __shared__ float s_res[3];

    float v = (tid < 128) ? g_maxQ[b * QL + tid] : NEG_INF;
    red[tid] = v; __syncthreads();
    for (int s = 128; s > 0; s >>= 1) { if (tid < s) red[tid] = fmaxf(red[tid], red[tid + s]); __syncthreads(); }
    float m = red[0]; __syncthreads();
    float e = (tid < 128) ? __expf(v - m) : 0.f;
    red[tid] = e; __syncthreads();
    for (int s = 128; s > 0; s >>= 1) { if (tid < s) red[tid] += red[tid + s]; __syncthreads(); }
    float ssum = red[0]; __syncthreads();
    if (tid < 128) wq[tid] = e / ssum;

    float va0 = g_maxA[b * AL + tid], va1 = g_maxA[b * AL + 256 + tid];
    red[tid] = fmaxf(va0, va1); __syncthreads();
    for (int s = 128; s > 0; s >>= 1) { if (tid < s) red[tid] = fmaxf(red[tid], red[tid + s]); __syncthreads(); }
    float mA = red[0]; __syncthreads();
    float ea0 = __expf(va0 - mA), ea1 = __expf(va1 - mA);
    red[tid] = ea0 + ea1; __syncthreads();
    for (int s = 128; s > 0; s >>= 1) { if (tid < s) red[tid] += red[tid + s]; __syncthreads(); }
    float sA = red[0]; __syncthreads();
    wa[tid] = ea0 / sA; wa[256 + tid] = ea1 / sA;
    __syncthreads();

    const int lane = tid & 31, wd = tid >> 5, sub = lane & 7, fl = lane >> 3;
    const float* Qb = g_Q + (size_t)b * FF * QL;
    const float* Ab = g_A + (size_t)b * FF * AL;
    for (int fb = wd * 4; fb < 400; fb += 32) {
        const int f = fb + fl;
        float accq = 0.f;
        for (int q = sub; q < QL; q += 8) accq += Qb[(size_t)f * QL + q] * wq[q];
        accq += __shfl_xor_sync(0xffffffffu, accq, 1);
        accq += __shfl_xor_sync(0xffffffffu, accq, 2);
        accq += __shfl_xor_sync(0xffffffffu, accq, 4);
        if (sub == 0) rq[f] = accq;
        float acca = 0.f;
        for (int a = sub; a < AL; a += 8) acca += Ab[(size_t)f * AL + a] * wa[a];
        acca += __shfl_xor_sync(0xffffffffu, acca, 1);
        acca += __shfl_xor_sync(0xffffffffu, acca, 2);
        acca += __shfl_xor_sync(0xffffffffu, acca, 4);
        if (sub == 0) ra[f] = acca;
    }
    __syncthreads();

    float dqa = 0.f, dqq = 0.f, daa = 0.f;
    for (int f = tid; f < 400; f += 256) {
        float x = rq[f], y = ra[f];
        dqa += x * y; dqq += x * x; daa += y * y;
    }
    red[tid] = dqa; __syncthreads();
    for (int s = 128; s > 0; s >>= 1) { if (tid < s) red[tid] += red[tid + s]; __syncthreads(); }
    if (tid == 0) s_res[0] = red[0];
    __syncthreads();
    red[tid] = dqq; __syncthreads();
    for (int s = 128; s > 0; s >>= 1) { if (tid < s) red[tid] += red[tid + s]; __syncthreads(); }
    if (tid == 0) s_res[1] = red[0];
    __syncthreads();
    red[tid] = daa; __syncthreads();
    for (int s = 128; s > 0; s >>= 1) { if (tid < s) red[tid] += red[tid + s]; __syncthreads(); }
    if (tid == 0) {
        s_res[2] = red[0];
        float nQ = fmaxf(sqrtf(s_res[1]), 1e-8f);
        float nA = fmaxf(sqrtf(s_res[2]), 1e-8f);
        out[b] = s_res[0] / (nQ * nA);
    }
}

// ---------------- launch -----------------------------------------------------
extern "C" void kernel_launch(void* const* d_in, const int* in_sizes, int n_in,
                              void* d_out, int out_size) {
    (void)in_sizes; (void)n_in; (void)out_size;
    const int*   question = (const int*)d_in[0];
    const int*   answer   = (const int*)d_in[1];
    const float* emb      = (const float*)d_in[2];
    const float* conv_w   = (const float*)d_in[3];
    const float* conv_b   = (const float*)d_in[4];
    const float* Umat     = (const float*)d_in[5];
    float* out = (float*)d_out;

    cudaFuncSetAttribute(gatherconv_kernel,
                         cudaFuncAttributeMaxDynamicSharedMemorySize, GA_SMEM);

    init_kernel<<<(EE * 1200 + 255) / 256, 256>>>(conv_w);
    transpose_emb_kernel<<<dim3(VPADT / 32, 10), dim3(32, 8)>>>(emb);
    tgemm_kernel<<<dim3(15, 391), 256>>>();
    gatherconv_kernel<<<dim3(20, 512), 256, GA_SMEM>>>(question, answer, conv_b);
    pgemm_kernel<<<dim3(4, 512), 256>>>(Umat);
    gmax_kernel<<<dim3(4, 512), 256>>>();
    final_kernel<<<512, 256>>>(out);
}

// round 15
// speedup vs baseline: 3.1054x; 1.0761x over previous
#include <cuda_runtime.h>
#include <cstdint>

#define BB 512
#define QL 128
#define AL 512
#define EE 300
#define FF 400
#define VV 50001
#define VMAX 50000
#define VPADT 50048           // 391*128
#define NEG_INF (-1e30f)

// ---------------- scratch (device globals; no allocations allowed) ----------
__device__ float g_Wt2[EE * 1200];                   // Wt2[e][k*400+f] (1.44 MB)
__device__ float g_embT[(size_t)EE * VPADT];         // emb transposed (60 MB)
__device__ float g_T[(size_t)VV * 1200];             // T[v][k][f] (240 MB)
__device__ float g_Q[(size_t)BB * FF * QL];          // 104.8 MB
__device__ float g_A[(size_t)BB * FF * AL];          // 419 MB
__device__ float g_P[(size_t)BB * FF * QL];          // 104.8 MB
__device__ float g_maxQ[BB * QL];
__device__ float g_maxA[BB * AL];

__device__ __forceinline__ void atomicMaxF(float* a, float v) {
    if (v >= 0.f) atomicMax((int*)a, __float_as_int(v));
    else          atomicMin((unsigned int*)a, __float_as_uint(v));
}

// ---------------- K0: build Wt2 + init maxes --------------------------------
__global__ void init_kernel(const float* __restrict__ conv_w) {
    int i = blockIdx.x * 256 + threadIdx.x;
    if (i < EE * 1200) {
        int e = i / 1200, rem = i - e * 1200;
        int k = rem / 400, f = rem - k * 400;
        g_Wt2[i] = conv_w[f * 900 + e * 3 + k];
    }
    if (i < BB * QL) g_maxQ[i] = NEG_INF;
    if (i < BB * AL) g_maxA[i] = NEG_INF;
}

// ---------------- K0b: transpose emb -> embT[e][v] --------------------------
__global__ void transpose_emb_kernel(const float* __restrict__ emb) {
    __shared__ float tile[32][33];
    const int v0 = blockIdx.x * 32, e0 = blockIdx.y * 32;
    const int tx = threadIdx.x, ty = threadIdx.y;
    #pragma unroll
    for (int i = ty; i < 32; i += 8) {
        int v = v0 + i, e = e0 + tx;
        tile[i][tx] = (v < VV && e < EE) ? emb[(size_t)v * EE + e] : 0.f;
    }
    __syncthreads();
    #pragma unroll
    for (int i = ty; i < 32; i += 8) {
        int e = e0 + i, v = v0 + tx;
        if (e < EE) g_embT[(size_t)e * VPADT + v] = tile[tx][i];
    }
}

// ---------------- K1a: T = emb @ Wt2  ([50001 x 300] @ [300 x 1200]) --------
__global__ __launch_bounds__(256) void tgemm_kernel() {
    const int tid = threadIdx.x;
    const int tn = tid & 15, tv = tid >> 4;
    const int n0 = blockIdx.x * 80;
    const int v0 = blockIdx.y * 128;
    __shared__ float Es[10 * 128];     // [e_local][v_local]
    __shared__ float Ws[10 * 80];      // [e_local][n_local]

    float acc[8][5];
    #pragma unroll
    for (int i = 0; i < 8; i++)
        #pragma unroll
        for (int j = 0; j < 5; j++) acc[i][j] = 0.f;

    for (int ec = 0; ec < 30; ec++) {
        const int e0 = ec * 10;
        __syncthreads();
        #pragma unroll
        for (int u = 0; u < 5; u++) {
            int idx = tid + 256 * u;            // 0..1279
            int e = idx >> 7, v = idx & 127;
            Es[idx] = g_embT[(size_t)(e0 + e) * VPADT + v0 + v];  // coalesced
        }
        #pragma unroll
        for (int t = tid; t < 800; t += 256) {
            int e = t / 80, n = t - e * 80;
            Ws[t] = g_Wt2[(e0 + e) * 1200 + n0 + n];
        }
        __syncthreads();
        #pragma unroll
        for (int e = 0; e < 10; e++) {
            float4 va = *(const float4*)&Es[e * 128 + tv * 8];
            float4 vb = *(const float4*)&Es[e * 128 + tv * 8 + 4];
            float vr[8] = {va.x, va.y, va.z, va.w, vb.x, vb.y, vb.z, vb.w};
            float wr[5];
            #pragma unroll
            for (int j = 0; j < 5; j++) wr[j] = Ws[e * 80 + tn * 5 + j];
            #pragma unroll
            for (int i = 0; i < 8; i++)
                #pragma unroll
                for (int j = 0; j < 5; j++)
                    acc[i][j] += vr[i] * wr[j];
        }
    }
    #pragma unroll
    for (int i = 0; i < 8; i++) {
        const int v = v0 + tv * 8 + i;
        if (v <= VMAX) {
            float* op = g_T + (size_t)v * 1200 + n0 + tn * 5;
            #pragma unroll
            for (int j = 0; j < 5; j++) op[j] = acc[i][j];
        }
    }
}

// ---------------- gather body: sync-free register accumulation --------------
// Thread owns f = 2*tid, 2*tid+1 (tid < 200). acc[dl] += T[toks[dl+k]][k][f].
// Full unroll -> static acc indices; zero in-loop syncthreads.
__device__ __forceinline__ void gather_body(
    const int* __restrict__ ip, int L, int l0, float* __restrict__ outp,
    const float* __restrict__ bias, int tid, int* toks)
{
    if (tid < 34) {
        int p = l0 - 1 + tid;
        int id = 0;                         // token 0 row of T is all zeros
        if (p >= 0 && p < L) {
            id = ip[p];
            if (id < 0) id = 0;
            if (id > VMAX) id = VMAX;
        }
        toks[tid] = id;
    }
    __syncthreads();
    if (tid >= 200) return;
    const int f0 = 2 * tid;
    const float b0 = bias[f0], b1 = bias[f0 + 1];
    float acc0[32], acc1[32];
    #pragma unroll
    for (int l = 0; l < 32; l++) { acc0[l] = b0; acc1[l] = b1; }

    #pragma unroll
    for (int r = 0; r < 34; r++) {
        const float* row = g_T + (size_t)toks[r] * 1200 + f0;
        float2 v0 = *(const float2*)(row);          // k=0
        float2 v1 = *(const float2*)(row + 400);    // k=1
        float2 v2 = *(const float2*)(row + 800);    // k=2
        if (r < 32)  { acc0[r]     += v0.x; acc1[r]     += v0.y; }
        if (r >= 1 && r <= 32) { acc0[r - 1] += v1.x; acc1[r - 1] += v1.y; }
        if (r >= 2)  { acc0[r - 2] += v2.x; acc1[r - 2] += v2.y; }
    }

    float* o0 = outp + (size_t)f0 * L + l0;
    float* o1 = outp + (size_t)(f0 + 1) * L + l0;
    #pragma unroll
    for (int l = 0; l < 32; l += 4) {
        float4 w0 = {acc0[l], acc0[l + 1], acc0[l + 2], acc0[l + 3]};
        float4 w1 = {acc1[l], acc1[l + 1], acc1[l + 2], acc1[l + 3]};
        *(float4*)(o0 + l) = w0;
        *(float4*)(o1 + l) = w1;
    }
}

// ---------------- K1b: gather-conv for Q ------------------------------------
__global__ __launch_bounds__(256) void gatherQ_kernel(
    const int* __restrict__ qidx, const float* __restrict__ bias)
{
    __shared__ int toks[34];
    const int lt = blockIdx.x, b = blockIdx.y;
    gather_body(qidx + b * QL, QL, lt * 32, g_Q + (size_t)b * FF * QL,
                bias, threadIdx.x, toks);
}

// ---------------- K2: fused pgemm (blocks 0..2047) + gather-A (2048..10239) -
// pgemm: P[b] = U^T @ Q[b]; compute-bound, launched first.
// gather-A: memory-bound; overlaps with pgemm on the same SMs.
__global__ __launch_bounds__(256) void fused_pgemm_gatherA_kernel(
    const float* __restrict__ Umat, const int* __restrict__ aidx,
    const float* __restrict__ bias)
{
    __shared__ float Us[8 * 128];
    __shared__ float Qs[8 * 128];
    __shared__ int toks[34];
    const int tid = threadIdx.x;

    if (blockIdx.x >= 2048) {
        const int i = blockIdx.x - 2048;
        const int lt = i & 15, b = i >> 4;
        gather_body(aidx + b * AL, AL, lt * 32, g_A + (size_t)b * FF * AL,
                    bias, tid, toks);
        return;
    }

    // ---- pgemm branch ----
    const int tq = tid & 15, tg = tid >> 4;
    const int g0 = (blockIdx.x & 3) * 128;
    const int b = blockIdx.x >> 2;
    float acc[8][8];
    #pragma unroll
    for (int i = 0; i < 8; i++)
        #pragma unroll
        for (int j = 0; j < 8; j++) acc[i][j] = 0.f;

    const float* Qb = g_Q + (size_t)b * FF * QL;
    const int fq = tid >> 5, q4 = (tid & 31) * 4;
    for (int fc = 0; fc < 50; fc++) {
        const int fbase = fc * 8;
        __syncthreads();
        #pragma unroll
        for (int u = 0; u < 4; u++) {
            int t = tid + 256 * u;                    // 0..1023
            int f = t >> 7, g = t & 127;
            Us[t] = (g0 + g < FF) ? Umat[(fbase + f) * FF + g0 + g] : 0.f;
        }
        *(float4*)&Qs[fq * 128 + q4] = *(const float4*)(Qb + (size_t)(fbase + fq) * QL + q4);
        __syncthreads();
        #pragma unroll
        for (int f = 0; f < 8; f++) {
            float4 ua = *(const float4*)&Us[f * 128 + tg * 8];
            float4 ub = *(const float4*)&Us[f * 128 + tg * 8 + 4];
            float4 qa = *(const float4*)&Qs[f * 128 + tq * 8];
            float4 qb = *(const float4*)&Qs[f * 128 + tq * 8 + 4];
            float ur[8] = {ua.x, ua.y, ua.z, ua.w, ub.x, ub.y, ub.z, ub.w};
            float qr[8] = {qa.x, qa.y, qa.z, qa.w, qb.x, qb.y, qb.z, qb.w};
            #pragma unroll
            for (int i = 0; i < 8; i++)
                #pragma unroll
                for (int j = 0; j < 8; j++)
                    acc[i][j] += ur[i] * qr[j];
        }
    }
    float* Pb = g_P + (size_t)b * FF * QL;
    #pragma unroll
    for (int i = 0; i < 8; i++) {
        const int g = g0 + tg * 8 + i;
        if (g < FF) {
            float4 v0 = {acc[i][0], acc[i][1], acc[i][2], acc[i][3]};
            float4 v1 = {acc[i][4], acc[i][5], acc[i][6], acc[i][7]};
            *(float4*)(Pb + (size_t)g * QL + tq * 8) = v0;
            *(float4*)(Pb + (size_t)g * QL + tq * 8 + 4) = v1;
        }
    }
}

// ---------------- K3: G = tanh(P^T A) tile + row/col maxes ------------------
__global__ __launch_bounds__(256) void gmax_kernel() {
    const int tid = threadIdx.x;
    const int ta = tid & 15, tq = tid >> 4;
    const int a0 = blockIdx.x * 128;
    const int b = blockIdx.y;
    __shared__ float Ps[8 * 128], As[8 * 128];
    __shared__ float smq[128], sma[128];

    float acc[8][8];
    #pragma unroll
    for (int i = 0; i < 8; i++)
        #pragma unroll
        for (int j = 0; j < 8; j++) acc[i][j] = 0.f;

    const float* Pb = g_P + (size_t)b * FF * QL;
    const float* Ab = g_A + (size_t)b * FF * AL;
    const int fg = tid >> 5, c4 = (tid & 31) * 4;
    for (int gc = 0; gc < 50; gc++) {
        const int gbase = gc * 8;
        __syncthreads();
        *(float4*)&Ps[fg * 128 + c4] = *(const float4*)(Pb + (size_t)(gbase + fg) * QL + c4);
        *(float4*)&As[fg * 128 + c4] = *(const float4*)(Ab + (size_t)(gbase + fg) * AL + a0 + c4);
        __syncthreads();
        #pragma unroll
        for (int g = 0; g < 8; g++) {
            float4 pa = *(const float4*)&Ps[g * 128 + tq * 8];
            float4 pb = *(const float4*)&Ps[g * 128 + tq * 8 + 4];
            float4 aa = *(const float4*)&As[g * 128 + ta * 8];
            float4 ab = *(const float4*)&As[g * 128 + ta * 8 + 4];
            float pr[8] = {pa.x, pa.y, pa.z, pa.w, pb.x, pb.y, pb.z, pb.w};
            float ar[8] = {aa.x, aa.y, aa.z, aa.w, ab.x, ab.y, ab.z, ab.w};
            #pragma unroll
            for (int i = 0; i < 8; i++)
                #pragma unroll
                for (int j = 0; j < 8; j++)
                    acc[i][j] += pr[i] * ar[j];
        }
    }

    if (tid < 128) { smq[tid] = NEG_INF; sma[tid] = NEG_INF; }
    __syncthreads();

    // tanh is monotonic: max(tanh(x)) = tanh(max(x))
    float mq[8], ma[8];
    #pragma unroll
    for (int i = 0; i < 8; i++) mq[i] = NEG_INF;
    #pragma unroll
    for (int j = 0; j < 8; j++) ma[j] = NEG_INF;
    #pragma unroll
    for (int i = 0; i < 8; i++)
        #pragma unroll
        for (int j = 0; j < 8; j++) {
            mq[i] = fmaxf(mq[i], acc[i][j]);
            ma[j] = fmaxf(ma[j], acc[i][j]);
        }
    #pragma unroll
    for (int i = 0; i < 8; i++) atomicMaxF(&smq[tq * 8 + i], tanhf(mq[i]));
    #pragma unroll
    for (int j = 0; j < 8; j++) atomicMaxF(&sma[ta * 8 + j], tanhf(ma[j]));
    __syncthreads();
    if (tid < 128) {
        atomicMaxF(&g_maxQ[b * QL + tid], smq[tid]);
        atomicMaxF(&g_maxA[b * AL + a0 + tid], sma[tid]);
    }
}

// ---------------- K4: softmax + pooled rQ/rA + cosine -----------------------
__global__ __launch_bounds__(256) void final_kernel(float* __restrict__ out) {
    const int tid = threadIdx.x;
    const int b = blockIdx.x;
    __shared__ float wq[128], wa[512], rq[400], ra[400], red[256];
    __shared__ float s_res[3];

    float v = (tid < 128) ? g_maxQ[b * QL + tid] : NEG_INF;
    red[tid] = v; __syncthreads();
    for (int s = 128; s > 0; s >>= 1) { if (tid < s) red[tid] = fmaxf(red[tid], red[tid + s]); __syncthreads(); }
    float m = red[0]; __syncthreads();
    float e = (tid < 128) ? __expf(v - m) : 0.f;
    red[tid] = e; __syncthreads();
    for (int s = 128; s > 0; s >>= 1) { if (tid < s) red[tid] += red[tid + s]; __syncthreads(); }
    float ssum = red[0]; __syncthreads();
    if (tid < 128) wq[tid] = e / ssum;

    float va0 = g_maxA[b * AL + tid], va1 = g_maxA[b * AL + 256 + tid];
    red[tid] = fmaxf(va0, va1); __syncthreads();
    for (int s = 128; s > 0; s >>= 1) { if (tid < s) red[tid] = fmaxf(red[tid], red[tid + s]); __syncthreads(); }
    float mA = red[0]; __syncthreads();
    float ea0 = __expf(va0 - mA), ea1 = __expf(va1 - mA);
    red[tid] = ea0 + ea1; __syncthreads();
    for (int s = 128; s > 0; s >>= 1) { if (tid < s) red[tid] += red[tid + s]; __syncthreads(); }
    float sA = red[0]; __syncthreads();
    wa[tid] = ea0 / sA; wa[256 + tid] = ea1 / sA;
    __syncthreads();

    const int lane = tid & 31, wd = tid >> 5, sub = lane & 7, fl = lane >> 3;
    const float* Qb = g_Q + (size_t)b * FF * QL;
    const float* Ab = g_A + (size_t)b * FF * AL;
    for (int fb = wd * 4; fb < 400; fb += 32) {
        const int f = fb + fl;
        float accq = 0.f;
        for (int q = sub; q < QL; q += 8) accq += Qb[(size_t)f * QL + q] * wq[q];
        accq += __shfl_xor_sync(0xffffffffu, accq, 1);
        accq += __shfl_xor_sync(0xffffffffu, accq, 2);
        accq += __shfl_xor_sync(0xffffffffu, accq, 4);
        if (sub == 0) rq[f] = accq;
        float acca = 0.f;
        for (int a = sub; a < AL; a += 8) acca += Ab[(size_t)f * AL + a] * wa[a];
        acca += __shfl_xor_sync(0xffffffffu, acca, 1);
        acca += __shfl_xor_sync(0xffffffffu, acca, 2);
        acca += __shfl_xor_sync(0xffffffffu, acca, 4);
        if (sub == 0) ra[f] = acca;
    }
    __syncthreads();

    float dqa = 0.f, dqq = 0.f, daa = 0.f;
    for (int f = tid; f < 400; f += 256) {
        float x = rq[f], y = ra[f];
        dqa += x * y; dqq += x * x; daa += y * y;
    }
    red[tid] = dqa; __syncthreads();
    for (int s = 128; s > 0; s >>= 1) { if (tid < s) red[tid] += red[tid + s]; __syncthreads(); }
    if (tid == 0) s_res[0] = red[0];
    __syncthreads();
    red[tid] = dqq; __syncthreads();
    for (int s = 128; s > 0; s >>= 1) { if (tid < s) red[tid] += red[tid + s]; __syncthreads(); }
    if (tid == 0) s_res[1] = red[0];
    __syncthreads();
    red[tid] = daa; __syncthreads();
    for (int s = 128; s > 0; s >>= 1) { if (tid < s) red[tid] += red[tid + s]; __syncthreads(); }
    if (tid == 0) {
        s_res[2] = red[0];
        float nQ = fmaxf(sqrtf(s_res[1]), 1e-8f);
        float nA = fmaxf(sqrtf(s_res[2]), 1e-8f);
        out[b] = s_res[0] / (nQ * nA);
    }
}

// ---------------- launch -----------------------------------------------------
extern "C" void kernel_launch(void* const* d_in, const int* in_sizes, int n_in,
                              void* d_out, int out_size) {
    (void)in_sizes; (void)n_in; (void)out_size;
    const int*   question = (const int*)d_in[0];
    const int*   answer   = (const int*)d_in[1];
    const float* emb      = (const float*)d_in[2];
    const float* conv_w   = (const float*)d_in[3];
    const float* conv_b   = (const float*)d_in[4];
    const float* Umat     = (const float*)d_in[5];
    float* out = (float*)d_out;

    init_kernel<<<(EE * 1200 + 255) / 256, 256>>>(conv_w);
    transpose_emb_kernel<<<dim3(VPADT / 32, 10), dim3(32, 8)>>>(emb);
    tgemm_kernel<<<dim3(15, 391), 256>>>();
    gatherQ_kernel<<<dim3(4, 512), 256>>>(question, conv_b);
    fused_pgemm_gatherA_kernel<<<10240, 256>>>(Umat, answer, conv_b);
    gmax_kernel<<<dim3(4, 512), 256>>>();
    final_kernel<<<512, 256>>>(out);
}